// round 1
// baseline (speedup 1.0000x reference)
#include <cuda_runtime.h>
#include <cstdint>

#define NN 100000
#define EE 1600000
#define DD 64
#define ALPHA 0.9f
#define RES_SCALE 0.1f   // (1 - alpha), matches jax f32 rounding of python 0.1

// ---------------- static device scratch (no runtime allocation) ----------------
__device__ float d_bufA[NN * DD];       // feature buffer A (initial y lives here)
__device__ float d_bufB[NN * DD];       // feature buffer B
__device__ float d_res [NN * DD];       // (1-alpha)*y
__device__ int   d_deg   [NN];          // in-degree
__device__ float d_dis   [NN];          // deg^{-1/2} (0 if deg==0)
__device__ int   d_off   [NN + 1];      // CSR offsets by destination
__device__ int   d_cursor[NN];          // scatter cursors
__device__ int2  d_csr   [EE];          // packed {src, __float_as_int(norm)}
__device__ int   d_bsum  [256];         // scan block sums
__device__ int   d_flagU8;              // 1 if train_mask is 1 byte/elem

// ---------------- kernels ----------------
__global__ void k_zero(int n) {
    int i = blockIdx.x * blockDim.x + threadIdx.x;
    if (i < n) { d_deg[i] = 0; d_cursor[i] = 0; }
    if (i == 0) d_flagU8 = 0;
}

// If mask is int32 0/1, bytes at offsets 1..3 (mod 4) are always 0.
// If mask is uint8 bools, ~half of those bytes are 1 -> set flag.
__global__ void k_detect(const uchar4* __restrict__ m, int n4) {
    int i = blockIdx.x * blockDim.x + threadIdx.x;
    if (i < n4) {
        uchar4 v = m[i];
        if (v.y | v.z | v.w) d_flagU8 = 1;
    }
}

__global__ void k_deg(const int* __restrict__ col, int E) {
    int e = blockIdx.x * blockDim.x + threadIdx.x;
    if (e < E) atomicAdd(&d_deg[col[e]], 1);
}

__global__ void k_dis(int n) {
    int i = blockIdx.x * blockDim.x + threadIdx.x;
    if (i < n) {
        int dg = d_deg[i];
        d_dis[i] = (dg > 0) ? rsqrtf((float)dg) : 0.0f;
    }
}

// exclusive scan of d_deg -> d_off, three phases
__global__ void k_scan1(int n) {
    __shared__ int sh[1024];
    int t = threadIdx.x;
    int i = blockIdx.x * 1024 + t;
    int v = (i < n) ? d_deg[i] : 0;
    sh[t] = v;
    __syncthreads();
    for (int ofs = 1; ofs < 1024; ofs <<= 1) {
        int x = 0;
        if (t >= ofs) x = sh[t - ofs];
        __syncthreads();
        sh[t] += x;
        __syncthreads();
    }
    if (i < n) d_off[i] = sh[t] - v;             // exclusive within block
    if (t == 1023) d_bsum[blockIdx.x] = sh[t];   // block total
}

__global__ void k_scan2(int B, int n) {
    if (threadIdx.x == 0 && blockIdx.x == 0) {
        int acc = 0;
        for (int b = 0; b < B; b++) {
            int t = d_bsum[b];
            d_bsum[b] = acc;
            acc += t;
        }
        d_off[n] = acc;
    }
}

__global__ void k_scan3(int n) {
    int i = blockIdx.x * 1024 + threadIdx.x;
    if (i < n) d_off[i] += d_bsum[blockIdx.x];
}

__global__ void k_scatter(const int* __restrict__ row, const int* __restrict__ col, int E) {
    int e = blockIdx.x * blockDim.x + threadIdx.x;
    if (e < E) {
        int r = row[e], c = col[e];
        float nrm = d_dis[r] * d_dis[c];
        int pos = d_off[c] + atomicAdd(&d_cursor[c], 1);
        d_csr[pos] = make_int2(r, __float_as_int(nrm));
    }
}

__global__ void k_init(const void* __restrict__ maskp, const float* __restrict__ protos,
                       const int* __restrict__ labels, int n) {
    int idx = blockIdx.x * blockDim.x + threadIdx.x;   // over n*16 float4 slots
    if (idx >= n * 16) return;
    int node = idx >> 4;
    int q    = idx & 15;
    bool tr;
    if (d_flagU8) tr = ((const unsigned char*)maskp)[node] != 0;
    else          tr = ((const int*)maskp)[node] != 0;
    float4 v = make_float4(0.f, 0.f, 0.f, 0.f);
    if (tr) v = ((const float4*)protos)[labels[node] * 16 + q];
    ((float4*)d_bufA)[idx] = v;
    ((float4*)d_res)[idx]  = make_float4(RES_SCALE * v.x, RES_SCALE * v.y,
                                         RES_SCALE * v.z, RES_SCALE * v.w);
}

// One warp per node. phase: 0 = A->B, 1 = B->A, 2 = A->labelsOut (+mask/count)
__global__ __launch_bounds__(256) void k_layer(int phase, float* __restrict__ labelsOut,
                                               float* __restrict__ maskOut,
                                               float* __restrict__ cntOut, int n) {
    __shared__ int s_cnt;
    if (threadIdx.x == 0) s_cnt = 0;
    __syncthreads();

    int wid  = (blockIdx.x * blockDim.x + threadIdx.x) >> 5;
    int lane = threadIdx.x & 31;
    int last = (phase == 2);

    if (wid < n) {
        const float* in   = (phase == 1) ? d_bufB : d_bufA;
        float*       outp = (phase == 0) ? d_bufB : ((phase == 1) ? d_bufA : labelsOut);

        int start = d_off[wid];
        int end   = d_off[wid + 1];
        float ax = 0.f, ay = 0.f;

        for (int base = start; base < end; base += 32) {
            int idx = base + lane;
            int2 ent = (idx < end) ? d_csr[idx] : make_int2(0, 0);
            int cnt = min(32, end - base);
            #pragma unroll 4
            for (int j = 0; j < cnt; j++) {
                int   src = __shfl_sync(0xffffffffu, ent.x, j);
                float nrm = __int_as_float(__shfl_sync(0xffffffffu, ent.y, j));
                float2 v = __ldg((const float2*)(in + (size_t)src * DD) + lane);
                ax += nrm * v.x;
                ay += nrm * v.y;
            }
        }

        float2 r = *((const float2*)(d_res + (size_t)wid * DD) + lane);
        float ox = fminf(fmaxf(ALPHA * ax + r.x, 0.f), 1.f);
        float oy = fminf(fmaxf(ALPHA * ay + r.y, 0.f), 1.f);
        ((float2*)(outp + (size_t)wid * DD))[lane] = make_float2(ox, oy);

        if (last) {
            unsigned b = __ballot_sync(0xffffffffu, (ox == 0.f) && (oy == 0.f));
            if (lane == 0) {
                float m = (b == 0xffffffffu) ? 1.0f : 0.0f;
                maskOut[wid] = m;
                if (b == 0xffffffffu) atomicAdd(&s_cnt, 1);
            }
        }
    }
    __syncthreads();
    if (last && threadIdx.x == 0 && s_cnt) atomicAdd(cntOut, (float)s_cnt);
}

// ---------------- launch ----------------
extern "C" void kernel_launch(void* const* d_in, const int* in_sizes, int n_in,
                              void* d_out, int out_size) {
    const void*  maskp  = d_in[0];                 // bool [N] (u8 or i32, detected)
    const float* protos = (const float*)d_in[1];   // [C, D] f32
    const int*   labels = (const int*)d_in[2];     // [N] i32
    const int*   edges  = (const int*)d_in[3];     // [2, E] i32 row-major

    int N = in_sizes[0];
    int E = in_sizes[3] / 2;
    const int* row = edges;
    const int* col = edges + E;

    float* out       = (float*)d_out;
    float* labelsOut = out;                        // [N*D]
    float* cntOut    = out + (size_t)N * DD;       // [1]
    float* maskOut   = cntOut + 1;                 // [N]

    k_zero  <<<(N + 255) / 256, 256>>>(N);
    k_detect<<<((N / 4) + 255) / 256, 256>>>((const uchar4*)maskp, N / 4);
    k_deg   <<<(E + 255) / 256, 256>>>(col, E);
    k_dis   <<<(N + 255) / 256, 256>>>(N);

    int B = (N + 1023) / 1024;
    k_scan1<<<B, 1024>>>(N);
    k_scan2<<<1, 32>>>(B, N);
    k_scan3<<<B, 1024>>>(N);

    k_scatter<<<(E + 255) / 256, 256>>>(row, col, E);
    k_init   <<<((N * 16) + 255) / 256, 256>>>(maskp, protos, labels, N);

    cudaMemsetAsync(cntOut, 0, sizeof(float));

    int lb = (N + 7) / 8;                          // 8 warps (nodes) per 256-thread block
    k_layer<<<lb, 256>>>(0, labelsOut, maskOut, cntOut, N);
    k_layer<<<lb, 256>>>(1, labelsOut, maskOut, cntOut, N);
    k_layer<<<lb, 256>>>(2, labelsOut, maskOut, cntOut, N);
}

// round 2
// speedup vs baseline: 1.0982x; 1.0982x over previous
#include <cuda_runtime.h>
#include <cuda_fp16.h>
#include <cstdint>

#define NN 100000
#define EE 1600000
#define DD 64
#define ALPHA 0.9f
#define RES_SCALE 0.1f   // (1 - alpha)

// ---------------- static device scratch ----------------
__device__ __half2 d_hA[NN * 32];       // feature buffer A (half2 per 2 features)
__device__ __half2 d_hB[NN * 32];       // feature buffer B
__device__ float   d_res[NN * DD];      // (1-alpha)*y, fp32
__device__ int     d_deg   [NN];
__device__ float   d_dis   [NN];        // deg^{-1/2}
__device__ int     d_off   [NN + 1];
__device__ int     d_cursor[NN];
__device__ int2    d_csr   [EE];        // {src, __float_as_int(norm)}
__device__ int     d_bsum  [128];
__device__ int     d_flagU8;

// ---------------- kernels ----------------
// zero counters + detect mask dtype (int32 0/1 has zero bytes at offs 1..3)
__global__ void k_zero(const uchar4* __restrict__ m, int n) {
    int i = blockIdx.x * blockDim.x + threadIdx.x;
    if (i < n) { d_deg[i] = 0; d_cursor[i] = 0; }
    if (i == 0) d_flagU8 = 0;
    if (i < n / 4) {
        uchar4 v = m[i];
        if (v.y | v.z | v.w) d_flagU8 = 1;
    }
}

__global__ void k_deg(const int* __restrict__ col, int E) {
    int e = blockIdx.x * blockDim.x + threadIdx.x;
    if (e < E) atomicAdd(&d_deg[col[e]], 1);
}

// per-block exclusive scan of deg, also compute dis = rsqrt(deg)
__global__ void k_scan1(int n) {
    __shared__ int sh[1024];
    int t = threadIdx.x;
    int i = blockIdx.x * 1024 + t;
    int v = (i < n) ? d_deg[i] : 0;
    if (i < n) d_dis[i] = (v > 0) ? rsqrtf((float)v) : 0.0f;
    sh[t] = v;
    __syncthreads();
    for (int ofs = 1; ofs < 1024; ofs <<= 1) {
        int x = (t >= ofs) ? sh[t - ofs] : 0;
        __syncthreads();
        sh[t] += x;
        __syncthreads();
    }
    if (i < n) d_off[i] = sh[t] - v;
    if (t == 1023) d_bsum[blockIdx.x] = sh[t];
}

// parallel scan of <=128 block sums
__global__ void k_scan2(int B, int n) {
    __shared__ int sh[128];
    int t = threadIdx.x;
    int v = (t < B) ? d_bsum[t] : 0;
    sh[t] = v;
    __syncthreads();
    for (int ofs = 1; ofs < 128; ofs <<= 1) {
        int x = (t >= ofs) ? sh[t - ofs] : 0;
        __syncthreads();
        sh[t] += x;
        __syncthreads();
    }
    if (t < B) d_bsum[t] = sh[t] - v;    // exclusive
    if (t == 127) d_off[n] = sh[t];
}

__global__ void k_scan3(int n) {
    int i = blockIdx.x * 1024 + threadIdx.x;
    if (i < n) d_off[i] += d_bsum[blockIdx.x];
}

__global__ void k_scatter(const int* __restrict__ row, const int* __restrict__ col, int E) {
    int e = blockIdx.x * blockDim.x + threadIdx.x;
    if (e < E) {
        int r = row[e], c = col[e];
        float nrm = d_dis[r] * d_dis[c];
        int pos = d_off[c] + atomicAdd(&d_cursor[c], 1);
        d_csr[pos] = make_int2(r, __float_as_int(nrm));
    }
}

// init y (half) and res (fp32); also zero the output count slot
__global__ void k_init(const void* __restrict__ maskp, const float* __restrict__ protos,
                       const int* __restrict__ labels, float* __restrict__ cntOut, int n) {
    int idx = blockIdx.x * blockDim.x + threadIdx.x;   // over n*32 half2 / float2 slots
    if (idx == 0) cntOut[0] = 0.0f;
    if (idx >= n * 32) return;
    int node = idx >> 5;
    int q    = idx & 31;
    bool tr;
    if (d_flagU8) tr = ((const unsigned char*)maskp)[node] != 0;
    else          tr = ((const int*)maskp)[node] != 0;
    float2 v = make_float2(0.f, 0.f);
    if (tr) v = ((const float2*)protos)[labels[node] * 32 + q];
    d_hA[idx] = __floats2half2_rn(v.x, v.y);
    ((float2*)d_res)[idx] = make_float2(RES_SCALE * v.x, RES_SCALE * v.y);
}

// One warp per node, lane owns 2 features. phase: 0 A->B, 1 B->A, 2 A->out (+mask/count)
__global__ __launch_bounds__(256) void k_layer(int phase, float2* __restrict__ labelsOut,
                                               float* __restrict__ maskOut,
                                               float* __restrict__ cntOut, int n) {
    __shared__ int s_cnt;
    if (threadIdx.x == 0) s_cnt = 0;
    __syncthreads();

    int wid  = (blockIdx.x * blockDim.x + threadIdx.x) >> 5;
    int lane = threadIdx.x & 31;
    int last = (phase == 2);

    if (wid < n) {
        const __half2* in = (phase == 1) ? d_hB : d_hA;

        int start = d_off[wid];
        int end   = d_off[wid + 1];
        float ax = 0.f, ay = 0.f;

        for (int base = start; base < end; base += 32) {
            int idx = base + lane;
            int2 ent = (idx < end) ? d_csr[idx] : make_int2(0, 0);
            int cnt = min(32, end - base);
            #pragma unroll 8
            for (int j = 0; j < cnt; j++) {
                int   src = __shfl_sync(0xffffffffu, ent.x, j);
                float nrm = __int_as_float(__shfl_sync(0xffffffffu, ent.y, j));
                float2 v = __half22float2(__ldg(in + src * 32 + lane));
                ax += nrm * v.x;
                ay += nrm * v.y;
            }
        }

        float2 r = ((const float2*)d_res)[wid * 32 + lane];
        float ox = fminf(fmaxf(ALPHA * ax + r.x, 0.f), 1.f);
        float oy = fminf(fmaxf(ALPHA * ay + r.y, 0.f), 1.f);

        if (last) {
            labelsOut[wid * 32 + lane] = make_float2(ox, oy);
            unsigned b = __ballot_sync(0xffffffffu, (ox == 0.f) && (oy == 0.f));
            if (lane == 0) {
                maskOut[wid] = (b == 0xffffffffu) ? 1.0f : 0.0f;
                if (b == 0xffffffffu) atomicAdd(&s_cnt, 1);
            }
        } else {
            __half2* outp = (phase == 0) ? d_hB : d_hA;
            outp[wid * 32 + lane] = __floats2half2_rn(ox, oy);
        }
    }
    __syncthreads();
    if (last && threadIdx.x == 0 && s_cnt) atomicAdd(cntOut, (float)s_cnt);
}

// ---------------- launch ----------------
extern "C" void kernel_launch(void* const* d_in, const int* in_sizes, int n_in,
                              void* d_out, int out_size) {
    const void*  maskp  = d_in[0];                 // bool [N]
    const float* protos = (const float*)d_in[1];   // [C, D] f32
    const int*   labels = (const int*)d_in[2];     // [N] i32
    const int*   edges  = (const int*)d_in[3];     // [2, E] i32

    int N = in_sizes[0];
    int E = in_sizes[3] / 2;
    const int* row = edges;
    const int* col = edges + E;

    float* out       = (float*)d_out;
    float2* labelsOut= (float2*)out;               // [N*D]
    float* cntOut    = out + (size_t)N * DD;       // [1]
    float* maskOut   = cntOut + 1;                 // [N]

    k_zero<<<(N + 255) / 256, 256>>>((const uchar4*)maskp, N);
    k_deg <<<(E + 255) / 256, 256>>>(col, E);

    int B = (N + 1023) / 1024;
    k_scan1<<<B, 1024>>>(N);
    k_scan2<<<1, 128>>>(B, N);
    k_scan3<<<B, 1024>>>(N);

    k_scatter<<<(E + 255) / 256, 256>>>(row, col, E);
    k_init   <<<((N * 32) + 255) / 256, 256>>>(maskp, protos, labels, cntOut, N);

    int lb = (N + 7) / 8;
    k_layer<<<lb, 256>>>(0, labelsOut, maskOut, cntOut, N);
    k_layer<<<lb, 256>>>(1, labelsOut, maskOut, cntOut, N);
    k_layer<<<lb, 256>>>(2, labelsOut, maskOut, cntOut, N);
}

// round 5
// speedup vs baseline: 1.2720x; 1.1583x over previous
#include <cuda_runtime.h>
#include <cuda_fp16.h>
#include <cstdint>

#define NN 100000
#define EE 1600000
#define DD 64
#define ALPHA 0.9f
#define RES_SCALE 0.1f   // (1 - alpha)

// ---------------- helpers ----------------
__device__ __forceinline__ unsigned h2_to_u32(__half2 h) {
    union { __half2 h; unsigned u; } c; c.h = h; return c.u;
}
__device__ __forceinline__ float2 u32_to_f2(unsigned u) {
    union { unsigned u; __half2 h; } c; c.u = u;
    return __half22float2(c.h);
}

// ---------------- static device scratch ----------------
__device__ int4  d_hA[NN * 8];          // feature buffer A: 8 int4 = 64 halves per node
__device__ int4  d_hB[NN * 8];          // feature buffer B
__device__ int4  d_hR[NN * 8];          // (1-alpha)*y in half
__device__ int   d_cnt[2 * NN + 1];     // [0,N)=deg  [N,2N)=cursor  [2N]=flagU8 (memset 0)
__device__ float d_dis [NN];            // deg^{-1/2}
__device__ int   d_off [NN + 1];
__device__ int2  d_csr [EE];            // {src, __float_as_int(norm)}
__device__ int   d_bsum[128];

// ---------------- kernels ----------------
// degree histogram + mask dtype detection (int32 0/1 has zero bytes at offs 1..3)
__global__ void k_deg(const int* __restrict__ col, const uchar4* __restrict__ m,
                      int E, int n4) {
    int e = blockIdx.x * blockDim.x + threadIdx.x;
    if (e < E) atomicAdd(&d_cnt[col[e]], 1);
    if (e < n4) {
        uchar4 v = m[e];
        if (v.y | v.z | v.w) d_cnt[2 * NN] = 1;
    }
}

// per-block exclusive scan of deg; also dis = rsqrt(deg)
__global__ void k_scan1(int n) {
    __shared__ int sh[1024];
    int t = threadIdx.x;
    int i = blockIdx.x * 1024 + t;
    int v = (i < n) ? d_cnt[i] : 0;
    if (i < n) d_dis[i] = (v > 0) ? rsqrtf((float)v) : 0.0f;
    sh[t] = v;
    __syncthreads();
    for (int ofs = 1; ofs < 1024; ofs <<= 1) {
        int x = (t >= ofs) ? sh[t - ofs] : 0;
        __syncthreads();
        sh[t] += x;
        __syncthreads();
    }
    if (i < n) d_off[i] = sh[t] - v;
    if (t == 1023) d_bsum[blockIdx.x] = sh[t];
}

__global__ void k_scan2(int B, int n) {
    __shared__ int sh[128];
    int t = threadIdx.x;
    int v = (t < B) ? d_bsum[t] : 0;
    sh[t] = v;
    __syncthreads();
    for (int ofs = 1; ofs < 128; ofs <<= 1) {
        int x = (t >= ofs) ? sh[t - ofs] : 0;
        __syncthreads();
        sh[t] += x;
        __syncthreads();
    }
    if (t < B) d_bsum[t] = sh[t] - v;
    if (t == 127) d_off[n] = sh[t];
}

__global__ void k_scan3(int n) {
    int i = blockIdx.x * 1024 + threadIdx.x;
    if (i < n) d_off[i] += d_bsum[blockIdx.x];
}

__global__ void k_scatter(const int* __restrict__ row, const int* __restrict__ col, int E) {
    int e = blockIdx.x * blockDim.x + threadIdx.x;
    if (e < E) {
        int r = row[e], c = col[e];
        float nrm = d_dis[r] * d_dis[c];
        int pos = d_off[c] + atomicAdd(&d_cnt[NN + c], 1);
        d_csr[pos] = make_int2(r, __float_as_int(nrm));
    }
}

__device__ __forceinline__ int4 pack8(float4 a, float4 b) {
    int4 r;
    r.x = (int)h2_to_u32(__floats2half2_rn(a.x, a.y));
    r.y = (int)h2_to_u32(__floats2half2_rn(a.z, a.w));
    r.z = (int)h2_to_u32(__floats2half2_rn(b.x, b.y));
    r.w = (int)h2_to_u32(__floats2half2_rn(b.z, b.w));
    return r;
}

// init y (half) + res (half); zero out count slot
__global__ void k_init(const void* __restrict__ maskp, const float4* __restrict__ protos,
                       const int* __restrict__ labels, float* __restrict__ cntOut, int n) {
    int idx = blockIdx.x * blockDim.x + threadIdx.x;   // over n*8 int4 slots
    if (idx == 0) cntOut[0] = 0.0f;
    if (idx >= n * 8) return;
    int node = idx >> 3;
    int q    = idx & 7;
    bool tr;
    if (d_cnt[2 * NN]) tr = ((const unsigned char*)maskp)[node] != 0;
    else               tr = ((const int*)maskp)[node] != 0;
    float4 p0 = make_float4(0.f, 0.f, 0.f, 0.f), p1 = p0;
    if (tr) {
        int base = labels[node] * 16 + q * 2;          // protos row = 16 float4
        p0 = protos[base];
        p1 = protos[base + 1];
    }
    d_hA[idx] = pack8(p0, p1);
    float4 r0 = make_float4(RES_SCALE * p0.x, RES_SCALE * p0.y, RES_SCALE * p0.z, RES_SCALE * p0.w);
    float4 r1 = make_float4(RES_SCALE * p1.x, RES_SCALE * p1.y, RES_SCALE * p1.z, RES_SCALE * p1.w);
    d_hR[idx] = pack8(r0, r1);
}

// 8 lanes per node; lane owns 8 features (int4). phase: 0 A->B, 1 B->A, 2 A->out
__global__ __launch_bounds__(256) void k_layer(int phase, float4* __restrict__ labelsOut,
                                               float* __restrict__ maskOut,
                                               float* __restrict__ cntOut, int n) {
    __shared__ int s_cnt;
    if (threadIdx.x == 0) s_cnt = 0;
    __syncthreads();

    int grp  = (blockIdx.x * blockDim.x + threadIdx.x) >> 3;   // node
    int gl   = threadIdx.x & 7;
    int laneInWarp = threadIdx.x & 31;
    // 8-lane subgroup mask: groups have divergent loop trips, so every
    // sync shuffle inside the edge loop MUST be scoped to the group.
    unsigned gmask = 0xFFu << (laneInWarp & ~7);
    bool last = (phase == 2);
    bool nonzero = false;

    if (grp < n) {
        const int4* in = (phase == 1) ? d_hB : d_hA;

        int start = d_off[grp];
        int end   = d_off[grp + 1];
        float2 acc[4] = {{0.f,0.f},{0.f,0.f},{0.f,0.f},{0.f,0.f}};

        for (int base = start; base < end; base += 8) {
            int idx = base + gl;
            int2 ent = (idx < end) ? d_csr[idx] : make_int2(0, 0);
            int cnt = min(8, end - base);
            #pragma unroll 8
            for (int j = 0; j < cnt; j++) {
                int   src = __shfl_sync(gmask, ent.x, j, 8);
                float nrm = __int_as_float(__shfl_sync(gmask, ent.y, j, 8));
                int4 pv = __ldg(in + src * 8 + gl);
                float2 f;
                f = u32_to_f2((unsigned)pv.x); acc[0].x += nrm * f.x; acc[0].y += nrm * f.y;
                f = u32_to_f2((unsigned)pv.y); acc[1].x += nrm * f.x; acc[1].y += nrm * f.y;
                f = u32_to_f2((unsigned)pv.z); acc[2].x += nrm * f.x; acc[2].y += nrm * f.y;
                f = u32_to_f2((unsigned)pv.w); acc[3].x += nrm * f.x; acc[3].y += nrm * f.y;
            }
        }

        int4 rv = __ldg(d_hR + grp * 8 + gl);
        float o[8];
        {
            const unsigned rw[4] = {(unsigned)rv.x, (unsigned)rv.y, (unsigned)rv.z, (unsigned)rv.w};
            #pragma unroll
            for (int k = 0; k < 4; k++) {
                float2 rf = u32_to_f2(rw[k]);
                o[2*k]   = fminf(fmaxf(ALPHA * acc[k].x + rf.x, 0.f), 1.f);
                o[2*k+1] = fminf(fmaxf(ALPHA * acc[k].y + rf.y, 0.f), 1.f);
            }
        }
        #pragma unroll
        for (int k = 0; k < 8; k++) nonzero |= (o[k] != 0.f);

        if (last) {
            labelsOut[grp * 16 + gl * 2]     = make_float4(o[0], o[1], o[2], o[3]);
            labelsOut[grp * 16 + gl * 2 + 1] = make_float4(o[4], o[5], o[6], o[7]);
        } else {
            int4* outp = (phase == 0) ? d_hB : d_hA;
            int4 w;
            w.x = (int)h2_to_u32(__floats2half2_rn(o[0], o[1]));
            w.y = (int)h2_to_u32(__floats2half2_rn(o[2], o[3]));
            w.z = (int)h2_to_u32(__floats2half2_rn(o[4], o[5]));
            w.w = (int)h2_to_u32(__floats2half2_rn(o[6], o[7]));
            outp[grp * 8 + gl] = w;
        }
    }

    if (last) {
        // warp is fully reconverged here; full-mask ballot is safe
        unsigned b = __ballot_sync(0xffffffffu, nonzero);
        unsigned gbits = (b >> (laneInWarp & ~7)) & 0xFFu;
        if (gl == 0 && grp < n) {
            bool notUpd = (gbits == 0u);
            maskOut[grp] = notUpd ? 1.0f : 0.0f;
            if (notUpd) atomicAdd(&s_cnt, 1);
        }
        __syncthreads();
        if (threadIdx.x == 0 && s_cnt) atomicAdd(cntOut, (float)s_cnt);
    }
}

// ---------------- launch ----------------
extern "C" void kernel_launch(void* const* d_in, const int* in_sizes, int n_in,
                              void* d_out, int out_size) {
    const void*  maskp  = d_in[0];                 // bool [N]
    const float* protos = (const float*)d_in[1];   // [C, D] f32
    const int*   labels = (const int*)d_in[2];     // [N] i32
    const int*   edges  = (const int*)d_in[3];     // [2, E] i32

    int N = in_sizes[0];
    int E = in_sizes[3] / 2;
    const int* row = edges;
    const int* col = edges + E;

    float*  out       = (float*)d_out;
    float4* labelsOut = (float4*)out;              // [N*D]
    float*  cntOut    = out + (size_t)N * DD;      // [1]
    float*  maskOut   = cntOut + 1;                // [N]

    void* cntPtr = nullptr;
    cudaGetSymbolAddress(&cntPtr, d_cnt);
    cudaMemsetAsync(cntPtr, 0, (2 * NN + 1) * sizeof(int));

    int degThreads = (E > N) ? E : N;
    k_deg<<<(degThreads + 255) / 256, 256>>>(col, (const uchar4*)maskp, E, N / 4);

    int B = (N + 1023) / 1024;
    k_scan1<<<B, 1024>>>(N);
    k_scan2<<<1, 128>>>(B, N);
    k_scan3<<<B, 1024>>>(N);

    k_scatter<<<(E + 255) / 256, 256>>>(row, col, E);
    k_init   <<<((N * 8) + 255) / 256, 256>>>(maskp, (const float4*)protos, labels, cntOut, N);

    int lb = (N * 8 + 255) / 256;                  // 8 threads per node
    k_layer<<<lb, 256>>>(0, labelsOut, maskOut, cntOut, N);
    k_layer<<<lb, 256>>>(1, labelsOut, maskOut, cntOut, N);
    k_layer<<<lb, 256>>>(2, labelsOut, maskOut, cntOut, N);
}

// round 6
// speedup vs baseline: 1.6473x; 1.2950x over previous
#include <cuda_runtime.h>
#include <cuda_fp16.h>
#include <cstdint>

#define NN 100000
#define EE 1600000
#define DD 64
#define ALPHA 0.9f
#define RES_SCALE 0.1f   // (1 - alpha)

// ---------------- helpers ----------------
__device__ __forceinline__ unsigned h2_to_u32(__half2 h) {
    union { __half2 h; unsigned u; } c; c.h = h; return c.u;
}
__device__ __forceinline__ float2 u32_to_f2(unsigned u) {
    union { unsigned u; __half2 h; } c; c.u = u;
    return __half22float2(c.h);
}

// ---------------- static device scratch ----------------
__device__ int4  d_hY[NN * 8];          // initial y (half): res source, layer-1 input
__device__ int4  d_hB[NN * 8];          // feature buffer B
__device__ int4  d_hC[NN * 8];          // feature buffer C
__device__ int   d_cnt[2 * NN + 1];     // [0,N)=deg  [N,2N)=cursor  [2N]=flagU8
__device__ float d_dis [NN];            // deg^{-1/2}
__device__ int   d_off [NN + 1];
__device__ int2  d_csr [EE];            // {src, __float_as_int(norm)}
__device__ int   d_bsum[128];

// ---------------- kernels ----------------
// degree histogram + mask dtype detection (int32 0/1 has zero bytes at offs 1..3)
__global__ void k_deg(const int* __restrict__ col, const uchar4* __restrict__ m,
                      int E, int n4) {
    int e = blockIdx.x * blockDim.x + threadIdx.x;
    if (e < E) atomicAdd(&d_cnt[col[e]], 1);
    if (e < n4) {
        uchar4 v = m[e];
        if (v.y | v.z | v.w) d_cnt[2 * NN] = 1;
    }
}

// phase A: per-block reduction of deg -> d_bsum[b]
__global__ void k_scanA(int n) {
    __shared__ int sh[1024];
    int t = threadIdx.x;
    int i = blockIdx.x * 1024 + t;
    sh[t] = (i < n) ? d_cnt[i] : 0;
    __syncthreads();
    for (int ofs = 512; ofs > 0; ofs >>= 1) {
        if (t < ofs) sh[t] += sh[t + ofs];
        __syncthreads();
    }
    if (t == 0) d_bsum[blockIdx.x] = sh[0];
}

// phase B: inline prefix of block sums + full tile scan; writes off, dis, cursor
__global__ void k_scanB(int n, int B) {
    __shared__ int sb[128];
    __shared__ int sh[1024];
    int t = threadIdx.x;
    int b = blockIdx.x;
    int i = b * 1024 + t;

    if (t < 128) sb[t] = (t < B) ? d_bsum[t] : 0;
    __syncthreads();
    for (int ofs = 1; ofs < 128; ofs <<= 1) {
        int x = (t < 128 && t >= ofs) ? sb[t - ofs] : 0;
        __syncthreads();
        if (t < 128) sb[t] += x;
        __syncthreads();
    }
    int pref = (b > 0) ? sb[b - 1] : 0;     // exclusive prefix for this block

    int v = (i < n) ? d_cnt[i] : 0;
    if (i < n) d_dis[i] = (v > 0) ? rsqrtf((float)v) : 0.0f;
    sh[t] = v;
    __syncthreads();
    for (int ofs = 1; ofs < 1024; ofs <<= 1) {
        int x = (t >= ofs) ? sh[t - ofs] : 0;
        __syncthreads();
        sh[t] += x;
        __syncthreads();
    }
    if (i < n) {
        int off = pref + sh[t] - v;
        d_off[i] = off;
        d_cnt[NN + i] = off;                // cursor seeded with offset
    }
    if (b == B - 1 && t == 1023) d_off[n] = pref + sh[t];
}

__global__ void k_scatter(const int* __restrict__ row, const int* __restrict__ col, int E) {
    int e = blockIdx.x * blockDim.x + threadIdx.x;
    if (e < E) {
        int r = row[e], c = col[e];
        float nrm = d_dis[r] * d_dis[c];
        int pos = atomicAdd(&d_cnt[NN + c], 1);
        d_csr[pos] = make_int2(r, __float_as_int(nrm));
    }
}

__device__ __forceinline__ int4 pack8(float4 a, float4 b) {
    int4 r;
    r.x = (int)h2_to_u32(__floats2half2_rn(a.x, a.y));
    r.y = (int)h2_to_u32(__floats2half2_rn(a.z, a.w));
    r.z = (int)h2_to_u32(__floats2half2_rn(b.x, b.y));
    r.w = (int)h2_to_u32(__floats2half2_rn(b.z, b.w));
    return r;
}

// init y (half); zero out count slot
__global__ void k_init(const void* __restrict__ maskp, const float4* __restrict__ protos,
                       const int* __restrict__ labels, float* __restrict__ cntOut, int n) {
    int idx = blockIdx.x * blockDim.x + threadIdx.x;   // over n*8 int4 slots
    if (idx == 0) cntOut[0] = 0.0f;
    if (idx >= n * 8) return;
    int node = idx >> 3;
    int q    = idx & 7;
    bool tr;
    if (d_cnt[2 * NN]) tr = ((const unsigned char*)maskp)[node] != 0;
    else               tr = ((const int*)maskp)[node] != 0;
    float4 p0 = make_float4(0.f, 0.f, 0.f, 0.f), p1 = p0;
    if (tr) {
        int base = labels[node] * 16 + q * 2;          // protos row = 16 float4
        p0 = protos[base];
        p1 = protos[base + 1];
    }
    d_hY[idx] = pack8(p0, p1);
}

// 8 lanes per node; lane owns 8 features (int4).
// phase 0: Y->B, 1: B->C, 2: C->out (+mask/count). res = 0.1 * Y[node].
__global__ __launch_bounds__(256) void k_layer(int phase, float4* __restrict__ labelsOut,
                                               float* __restrict__ maskOut,
                                               float* __restrict__ cntOut, int n) {
    __shared__ int s_cnt;
    if (threadIdx.x == 0) s_cnt = 0;
    __syncthreads();

    int grp  = (blockIdx.x * blockDim.x + threadIdx.x) >> 3;   // node
    int gl   = threadIdx.x & 7;
    int laneInWarp = threadIdx.x & 31;
    bool last = (phase == 2);
    bool nonzero = false;

    if (grp < n) {
        const int4* in = (phase == 0) ? d_hY : ((phase == 1) ? d_hB : d_hC);

        int start = d_off[grp];
        int end   = d_off[grp + 1];
        float2 acc[4] = {{0.f,0.f},{0.f,0.f},{0.f,0.f},{0.f,0.f}};

        #pragma unroll 4
        for (int e = start; e < end; ++e) {
            int2 ent = __ldg(&d_csr[e]);               // uniform in 8-lane group: bcast
            float nrm = __int_as_float(ent.y);
            int4 pv = __ldg(in + ent.x * 8 + gl);
            float2 f;
            f = u32_to_f2((unsigned)pv.x); acc[0].x += nrm * f.x; acc[0].y += nrm * f.y;
            f = u32_to_f2((unsigned)pv.y); acc[1].x += nrm * f.x; acc[1].y += nrm * f.y;
            f = u32_to_f2((unsigned)pv.z); acc[2].x += nrm * f.x; acc[2].y += nrm * f.y;
            f = u32_to_f2((unsigned)pv.w); acc[3].x += nrm * f.x; acc[3].y += nrm * f.y;
        }

        int4 rv = __ldg(d_hY + grp * 8 + gl);          // res source
        float o[8];
        {
            const unsigned rw[4] = {(unsigned)rv.x, (unsigned)rv.y, (unsigned)rv.z, (unsigned)rv.w};
            #pragma unroll
            for (int k = 0; k < 4; k++) {
                float2 rf = u32_to_f2(rw[k]);
                o[2*k]   = fminf(fmaxf(ALPHA * acc[k].x + RES_SCALE * rf.x, 0.f), 1.f);
                o[2*k+1] = fminf(fmaxf(ALPHA * acc[k].y + RES_SCALE * rf.y, 0.f), 1.f);
            }
        }
        #pragma unroll
        for (int k = 0; k < 8; k++) nonzero |= (o[k] != 0.f);

        if (last) {
            labelsOut[grp * 16 + gl * 2]     = make_float4(o[0], o[1], o[2], o[3]);
            labelsOut[grp * 16 + gl * 2 + 1] = make_float4(o[4], o[5], o[6], o[7]);
        } else {
            int4* outp = (phase == 0) ? d_hB : d_hC;
            int4 w;
            w.x = (int)h2_to_u32(__floats2half2_rn(o[0], o[1]));
            w.y = (int)h2_to_u32(__floats2half2_rn(o[2], o[3]));
            w.z = (int)h2_to_u32(__floats2half2_rn(o[4], o[5]));
            w.w = (int)h2_to_u32(__floats2half2_rn(o[6], o[7]));
            outp[grp * 8 + gl] = w;
        }
    }

    if (last) {
        // warp fully reconverged; full-mask ballot safe
        unsigned bmask = __ballot_sync(0xffffffffu, nonzero);
        unsigned gbits = (bmask >> (laneInWarp & ~7)) & 0xFFu;
        if (gl == 0 && grp < n) {
            bool notUpd = (gbits == 0u);
            maskOut[grp] = notUpd ? 1.0f : 0.0f;
            if (notUpd) atomicAdd(&s_cnt, 1);
        }
        __syncthreads();
        if (threadIdx.x == 0 && s_cnt) atomicAdd(cntOut, (float)s_cnt);
    }
}

// ---------------- launch ----------------
extern "C" void kernel_launch(void* const* d_in, const int* in_sizes, int n_in,
                              void* d_out, int out_size) {
    const void*  maskp  = d_in[0];                 // bool [N]
    const float* protos = (const float*)d_in[1];   // [C, D] f32
    const int*   labels = (const int*)d_in[2];     // [N] i32
    const int*   edges  = (const int*)d_in[3];     // [2, E] i32

    int N = in_sizes[0];
    int E = in_sizes[3] / 2;
    const int* row = edges;
    const int* col = edges + E;

    float*  out       = (float*)d_out;
    float4* labelsOut = (float4*)out;              // [N*D]
    float*  cntOut    = out + (size_t)N * DD;      // [1]
    float*  maskOut   = cntOut + 1;                // [N]

    void* cntPtr = nullptr;
    cudaGetSymbolAddress(&cntPtr, d_cnt);
    // only deg region + flag must be zero (cursor gets overwritten by scanB)
    cudaMemsetAsync(cntPtr, 0, NN * sizeof(int));
    cudaMemsetAsync((char*)cntPtr + 2 * NN * sizeof(int), 0, sizeof(int));

    k_deg<<<(E + 255) / 256, 256>>>(col, (const uchar4*)maskp, E, N / 4);

    int B = (N + 1023) / 1024;
    k_scanA<<<B, 1024>>>(N);
    k_scanB<<<B, 1024>>>(N, B);

    k_scatter<<<(E + 255) / 256, 256>>>(row, col, E);
    k_init   <<<((N * 8) + 255) / 256, 256>>>(maskp, (const float4*)protos, labels, cntOut, N);

    int lb = (N * 8 + 255) / 256;                  // 8 threads per node
    k_layer<<<lb, 256>>>(0, labelsOut, maskOut, cntOut, N);
    k_layer<<<lb, 256>>>(1, labelsOut, maskOut, cntOut, N);
    k_layer<<<lb, 256>>>(2, labelsOut, maskOut, cntOut, N);
}

// round 7
// speedup vs baseline: 1.8058x; 1.0962x over previous
#include <cuda_runtime.h>
#include <cuda_fp16.h>
#include <cstdint>

#define NN 100000
#define EE 1600000
#define DD 64
#define ALPHA 0.9f
#define RES_SCALE 0.1f   // (1 - alpha)

// ---------------- helpers ----------------
__device__ __forceinline__ unsigned h2_to_u32(__half2 h) {
    union { __half2 h; unsigned u; } c; c.h = h; return c.u;
}
__device__ __forceinline__ float2 u32_to_f2(unsigned u) {
    union { unsigned u; __half2 h; } c; c.u = u;
    return __half22float2(c.h);
}

// ---------------- static device scratch ----------------
__device__ int4  d_hY[NN * 8];          // initial y (half, unscaled): res + layer-0 input
__device__ int4  d_hB[NN * 8];          // buffer B (stores dis*out)
__device__ int4  d_hC[NN * 8];          // buffer C (stores dis*out)
__device__ int   d_cnt[NN + 1];         // [0,N)=deg, [N]=flagU8  (single memset)
__device__ int   d_cur[NN];             // scatter cursor (seeded by scanB)
__device__ float d_dis[NN];             // deg^{-1/2}
__device__ int   d_off[NN + 1];
__device__ int   d_csr[EE];             // src only (4 B/edge)
__device__ int   d_bsum[128];

// ---------------- kernels ----------------
__global__ void k_deg(const int* __restrict__ col, const uchar4* __restrict__ m,
                      int E, int n4) {
    int e = blockIdx.x * blockDim.x + threadIdx.x;
    if (e < E) atomicAdd(&d_cnt[col[e]], 1);
    if (e < n4) {
        uchar4 v = m[e];
        if (v.y | v.z | v.w) d_cnt[NN] = 1;
    }
}

// phase A: per-block reduction of deg -> d_bsum[b]
__global__ void k_scanA(int n) {
    __shared__ int sh[1024];
    int t = threadIdx.x;
    int i = blockIdx.x * 1024 + t;
    sh[t] = (i < n) ? d_cnt[i] : 0;
    __syncthreads();
    for (int ofs = 512; ofs > 0; ofs >>= 1) {
        if (t < ofs) sh[t] += sh[t + ofs];
        __syncthreads();
    }
    if (t == 0) d_bsum[blockIdx.x] = sh[0];
}

// phase B: inline prefix of block sums + tile scan; writes off, dis, cursor
__global__ void k_scanB(int n, int B) {
    __shared__ int sb[128];
    __shared__ int sh[1024];
    int t = threadIdx.x;
    int b = blockIdx.x;
    int i = b * 1024 + t;

    if (t < 128) sb[t] = (t < B) ? d_bsum[t] : 0;
    __syncthreads();
    for (int ofs = 1; ofs < 128; ofs <<= 1) {
        int x = (t < 128 && t >= ofs) ? sb[t - ofs] : 0;
        __syncthreads();
        if (t < 128) sb[t] += x;
        __syncthreads();
    }
    int pref = (b > 0) ? sb[b - 1] : 0;

    int v = (i < n) ? d_cnt[i] : 0;
    if (i < n) d_dis[i] = (v > 0) ? rsqrtf((float)v) : 0.0f;
    sh[t] = v;
    __syncthreads();
    for (int ofs = 1; ofs < 1024; ofs <<= 1) {
        int x = (t >= ofs) ? sh[t - ofs] : 0;
        __syncthreads();
        sh[t] += x;
        __syncthreads();
    }
    if (i < n) {
        int off = pref + sh[t] - v;
        d_off[i] = off;
        d_cur[i] = off;
    }
    if (b == B - 1 && t == 1023) d_off[n] = pref + sh[t];
}

// scatter src only; no dis dependency
__global__ void k_scatter(const int* __restrict__ row, const int* __restrict__ col, int E) {
    int e = blockIdx.x * blockDim.x + threadIdx.x;
    if (e < E) {
        int pos = atomicAdd(&d_cur[col[e]], 1);
        d_csr[pos] = row[e];
    }
}

__device__ __forceinline__ int4 pack8(float4 a, float4 b) {
    int4 r;
    r.x = (int)h2_to_u32(__floats2half2_rn(a.x, a.y));
    r.y = (int)h2_to_u32(__floats2half2_rn(a.z, a.w));
    r.z = (int)h2_to_u32(__floats2half2_rn(b.x, b.y));
    r.w = (int)h2_to_u32(__floats2half2_rn(b.z, b.w));
    return r;
}

__global__ void k_init(const void* __restrict__ maskp, const float4* __restrict__ protos,
                       const int* __restrict__ labels, float* __restrict__ cntOut, int n) {
    int idx = blockIdx.x * blockDim.x + threadIdx.x;
    if (idx == 0) cntOut[0] = 0.0f;
    if (idx >= n * 8) return;
    int node = idx >> 3;
    int q    = idx & 7;
    bool tr;
    if (d_cnt[NN]) tr = ((const unsigned char*)maskp)[node] != 0;
    else           tr = ((const int*)maskp)[node] != 0;
    float4 p0 = make_float4(0.f, 0.f, 0.f, 0.f), p1 = p0;
    if (tr) {
        int base = labels[node] * 16 + q * 2;
        p0 = protos[base];
        p1 = protos[base + 1];
    }
    d_hY[idx] = pack8(p0, p1);
}

// 8 lanes per node; lane owns 8 features (int4).
// Buffers B/C hold dis-premultiplied features; Y is unscaled.
// phase 0: Y->B (per-edge dis[src]); 1: B->C; 2: C->out (+mask/count).
__global__ __launch_bounds__(256) void k_layer(int phase, float4* __restrict__ labelsOut,
                                               float* __restrict__ maskOut,
                                               float* __restrict__ cntOut, int n) {
    __shared__ int s_cnt;
    if (threadIdx.x == 0) s_cnt = 0;
    __syncthreads();

    int grp  = (blockIdx.x * blockDim.x + threadIdx.x) >> 3;
    int gl   = threadIdx.x & 7;
    int laneInWarp = threadIdx.x & 31;
    bool last = (phase == 2);
    bool nonzero = false;

    if (grp < n) {
        const int4* in = (phase == 0) ? d_hY : ((phase == 1) ? d_hB : d_hC);

        int start = d_off[grp];
        int end   = d_off[grp + 1];
        float2 acc[4] = {{0.f,0.f},{0.f,0.f},{0.f,0.f},{0.f,0.f}};

        if (phase == 0) {
            #pragma unroll 4
            for (int e = start; e < end; ++e) {
                int src = __ldg(&d_csr[e]);            // uniform in group: bcast
                float s = __ldg(&d_dis[src]);
                int4 pv = __ldg(in + src * 8 + gl);
                float2 f;
                f = u32_to_f2((unsigned)pv.x); acc[0].x += s * f.x; acc[0].y += s * f.y;
                f = u32_to_f2((unsigned)pv.y); acc[1].x += s * f.x; acc[1].y += s * f.y;
                f = u32_to_f2((unsigned)pv.z); acc[2].x += s * f.x; acc[2].y += s * f.y;
                f = u32_to_f2((unsigned)pv.w); acc[3].x += s * f.x; acc[3].y += s * f.y;
            }
        } else {
            #pragma unroll 4
            for (int e = start; e < end; ++e) {
                int src = __ldg(&d_csr[e]);
                int4 pv = __ldg(in + src * 8 + gl);
                float2 f;
                f = u32_to_f2((unsigned)pv.x); acc[0].x += f.x; acc[0].y += f.y;
                f = u32_to_f2((unsigned)pv.y); acc[1].x += f.x; acc[1].y += f.y;
                f = u32_to_f2((unsigned)pv.z); acc[2].x += f.x; acc[2].y += f.y;
                f = u32_to_f2((unsigned)pv.w); acc[3].x += f.x; acc[3].y += f.y;
            }
        }

        float disg = __ldg(&d_dis[grp]);
        float sc = ALPHA * disg;

        int4 rv = __ldg(d_hY + grp * 8 + gl);          // res source
        float o[8];
        {
            const unsigned rw[4] = {(unsigned)rv.x, (unsigned)rv.y, (unsigned)rv.z, (unsigned)rv.w};
            #pragma unroll
            for (int k = 0; k < 4; k++) {
                float2 rf = u32_to_f2(rw[k]);
                o[2*k]   = fminf(fmaxf(sc * acc[k].x + RES_SCALE * rf.x, 0.f), 1.f);
                o[2*k+1] = fminf(fmaxf(sc * acc[k].y + RES_SCALE * rf.y, 0.f), 1.f);
            }
        }
        #pragma unroll
        for (int k = 0; k < 8; k++) nonzero |= (o[k] != 0.f);

        if (last) {
            labelsOut[grp * 16 + gl * 2]     = make_float4(o[0], o[1], o[2], o[3]);
            labelsOut[grp * 16 + gl * 2 + 1] = make_float4(o[4], o[5], o[6], o[7]);
        } else {
            int4* outp = (phase == 0) ? d_hB : d_hC;
            int4 w;    // store dis-premultiplied features for next layer
            w.x = (int)h2_to_u32(__floats2half2_rn(disg * o[0], disg * o[1]));
            w.y = (int)h2_to_u32(__floats2half2_rn(disg * o[2], disg * o[3]));
            w.z = (int)h2_to_u32(__floats2half2_rn(disg * o[4], disg * o[5]));
            w.w = (int)h2_to_u32(__floats2half2_rn(disg * o[6], disg * o[7]));
            outp[grp * 8 + gl] = w;
        }
    }

    if (last) {
        unsigned bmask = __ballot_sync(0xffffffffu, nonzero);
        unsigned gbits = (bmask >> (laneInWarp & ~7)) & 0xFFu;
        if (gl == 0 && grp < n) {
            bool notUpd = (gbits == 0u);
            maskOut[grp] = notUpd ? 1.0f : 0.0f;
            if (notUpd) atomicAdd(&s_cnt, 1);
        }
        __syncthreads();
        if (threadIdx.x == 0 && s_cnt) atomicAdd(cntOut, (float)s_cnt);
    }
}

// ---------------- launch ----------------
extern "C" void kernel_launch(void* const* d_in, const int* in_sizes, int n_in,
                              void* d_out, int out_size) {
    const void*  maskp  = d_in[0];                 // bool [N]
    const float* protos = (const float*)d_in[1];   // [C, D] f32
    const int*   labels = (const int*)d_in[2];     // [N] i32
    const int*   edges  = (const int*)d_in[3];     // [2, E] i32

    int N = in_sizes[0];
    int E = in_sizes[3] / 2;
    const int* row = edges;
    const int* col = edges + E;

    float*  out       = (float*)d_out;
    float4* labelsOut = (float4*)out;              // [N*D]
    float*  cntOut    = out + (size_t)N * DD;      // [1]
    float*  maskOut   = cntOut + 1;                // [N]

    void* cntPtr = nullptr;
    cudaGetSymbolAddress(&cntPtr, d_cnt);
    cudaMemsetAsync(cntPtr, 0, (NN + 1) * sizeof(int));   // deg + flag

    k_deg<<<(E + 255) / 256, 256>>>(col, (const uchar4*)maskp, E, N / 4);

    int B = (N + 1023) / 1024;
    k_scanA<<<B, 1024>>>(N);
    k_scanB<<<B, 1024>>>(N, B);

    k_scatter<<<(E + 255) / 256, 256>>>(row, col, E);
    k_init   <<<((N * 8) + 255) / 256, 256>>>(maskp, (const float4*)protos, labels, cntOut, N);

    int lb = (N * 8 + 255) / 256;
    k_layer<<<lb, 256>>>(0, labelsOut, maskOut, cntOut, N);
    k_layer<<<lb, 256>>>(1, labelsOut, maskOut, cntOut, N);
    k_layer<<<lb, 256>>>(2, labelsOut, maskOut, cntOut, N);
}

// round 8
// speedup vs baseline: 1.8154x; 1.0053x over previous
#include <cuda_runtime.h>
#include <cuda_fp16.h>
#include <cstdint>

#define NN 100000
#define EE 1600000
#define DD 64
#define ALPHA 0.9f
#define RES_SCALE 0.1f   // (1 - alpha)

// ---------------- helpers ----------------
__device__ __forceinline__ unsigned h2_to_u32(__half2 h) {
    union { __half2 h; unsigned u; } c; c.h = h; return c.u;
}
__device__ __forceinline__ float2 u32_to_f2(unsigned u) {
    union { unsigned u; __half2 h; } c; c.u = u;
    return __half22float2(c.h);
}

// ---------------- static device scratch ----------------
__device__ int4  d_hY[NN * 8];          // initial y (half, unscaled): res + layer-0 input
__device__ int4  d_hB[NN * 8];          // buffer B (stores dis*out)
__device__ int4  d_hC[NN * 8];          // buffer C (stores dis*out)
__device__ int   d_cnt[NN + 1];         // [0,N)=deg, [N]=flagU8 (memset)
__device__ float d_dis[NN];             // deg^{-1/2}
__device__ int   d_off[NN + 1];
__device__ int   d_csr[EE];             // src only (4 B/edge)
__device__ int   d_rank[EE];            // edge rank within its destination
__device__ int   d_bsum[128];

// ---------------- kernels ----------------
// degree histogram capturing per-edge rank + mask dtype detect
__global__ void k_deg(const int4* __restrict__ col4, const uchar4* __restrict__ m,
                      int E4, int n4) {
    int i = blockIdx.x * blockDim.x + threadIdx.x;
    if (i < E4) {
        int4 c = col4[i];
        int4 r;
        r.x = atomicAdd(&d_cnt[c.x], 1);
        r.y = atomicAdd(&d_cnt[c.y], 1);
        r.z = atomicAdd(&d_cnt[c.z], 1);
        r.w = atomicAdd(&d_cnt[c.w], 1);
        ((int4*)d_rank)[i] = r;
    }
    if (i < n4) {
        uchar4 v = m[i];
        if (v.y | v.z | v.w) d_cnt[NN] = 1;
    }
}

// phase A: per-block reduction of deg -> d_bsum[b]
__global__ void k_scanA(int n) {
    __shared__ int sh[1024];
    int t = threadIdx.x;
    int i = blockIdx.x * 1024 + t;
    sh[t] = (i < n) ? d_cnt[i] : 0;
    __syncthreads();
    for (int ofs = 512; ofs > 0; ofs >>= 1) {
        if (t < ofs) sh[t] += sh[t + ofs];
        __syncthreads();
    }
    if (t == 0) d_bsum[blockIdx.x] = sh[0];
}

// phase B: inline prefix of block sums + tile scan; writes off, dis
__global__ void k_scanB(int n, int B) {
    __shared__ int sb[128];
    __shared__ int sh[1024];
    int t = threadIdx.x;
    int b = blockIdx.x;
    int i = b * 1024 + t;

    if (t < 128) sb[t] = (t < B) ? d_bsum[t] : 0;
    __syncthreads();
    for (int ofs = 1; ofs < 128; ofs <<= 1) {
        int x = (t < 128 && t >= ofs) ? sb[t - ofs] : 0;
        __syncthreads();
        if (t < 128) sb[t] += x;
        __syncthreads();
    }
    int pref = (b > 0) ? sb[b - 1] : 0;

    int v = (i < n) ? d_cnt[i] : 0;
    if (i < n) d_dis[i] = (v > 0) ? rsqrtf((float)v) : 0.0f;
    sh[t] = v;
    __syncthreads();
    for (int ofs = 1; ofs < 1024; ofs <<= 1) {
        int x = (t >= ofs) ? sh[t - ofs] : 0;
        __syncthreads();
        sh[t] += x;
        __syncthreads();
    }
    if (i < n) d_off[i] = pref + sh[t] - v;
    if (b == B - 1 && t == 1023) d_off[n] = pref + sh[t];
}

// atomic-free scatter: pos = off[col] + rank
__global__ void k_scatter(const int4* __restrict__ row4, const int4* __restrict__ col4,
                          int E4) {
    int i = blockIdx.x * blockDim.x + threadIdx.x;
    if (i < E4) {
        int4 c = col4[i];
        int4 r = row4[i];
        int4 k = ((const int4*)d_rank)[i];
        d_csr[__ldg(&d_off[c.x]) + k.x] = r.x;
        d_csr[__ldg(&d_off[c.y]) + k.y] = r.y;
        d_csr[__ldg(&d_off[c.z]) + k.z] = r.z;
        d_csr[__ldg(&d_off[c.w]) + k.w] = r.w;
    }
}

__device__ __forceinline__ int4 pack8(float4 a, float4 b) {
    int4 r;
    r.x = (int)h2_to_u32(__floats2half2_rn(a.x, a.y));
    r.y = (int)h2_to_u32(__floats2half2_rn(a.z, a.w));
    r.z = (int)h2_to_u32(__floats2half2_rn(b.x, b.y));
    r.w = (int)h2_to_u32(__floats2half2_rn(b.z, b.w));
    return r;
}

__global__ void k_init(const void* __restrict__ maskp, const float4* __restrict__ protos,
                       const int* __restrict__ labels, float* __restrict__ cntOut, int n) {
    int idx = blockIdx.x * blockDim.x + threadIdx.x;
    if (idx == 0) cntOut[0] = 0.0f;
    if (idx >= n * 8) return;
    int node = idx >> 3;
    int q    = idx & 7;
    bool tr;
    if (d_cnt[NN]) tr = ((const unsigned char*)maskp)[node] != 0;
    else           tr = ((const int*)maskp)[node] != 0;
    float4 p0 = make_float4(0.f, 0.f, 0.f, 0.f), p1 = p0;
    if (tr) {
        int base = labels[node] * 16 + q * 2;
        p0 = protos[base];
        p1 = protos[base + 1];
    }
    d_hY[idx] = pack8(p0, p1);
}

// 8 lanes per node; lane owns 8 features (int4).
// Buffers B/C hold dis-premultiplied features; Y is unscaled.
// phase 0: Y->B (per-edge dis[src]); 1: B->C; 2: C->out (+mask/count).
__global__ __launch_bounds__(256) void k_layer(int phase, float4* __restrict__ labelsOut,
                                               float* __restrict__ maskOut,
                                               float* __restrict__ cntOut, int n) {
    __shared__ int s_cnt;
    if (threadIdx.x == 0) s_cnt = 0;
    __syncthreads();

    int grp  = (blockIdx.x * blockDim.x + threadIdx.x) >> 3;
    int gl   = threadIdx.x & 7;
    int laneInWarp = threadIdx.x & 31;
    bool last = (phase == 2);
    bool nonzero = false;

    if (grp < n) {
        const int4* in = (phase == 0) ? d_hY : ((phase == 1) ? d_hB : d_hC);

        int start = d_off[grp];
        int end   = d_off[grp + 1];
        float2 acc[4] = {{0.f,0.f},{0.f,0.f},{0.f,0.f},{0.f,0.f}};

        if (phase == 0) {
            #pragma unroll 4
            for (int e = start; e < end; ++e) {
                int src = __ldg(&d_csr[e]);            // uniform in group: bcast
                float s = __ldg(&d_dis[src]);
                int4 pv = __ldg(in + src * 8 + gl);
                float2 f;
                f = u32_to_f2((unsigned)pv.x); acc[0].x += s * f.x; acc[0].y += s * f.y;
                f = u32_to_f2((unsigned)pv.y); acc[1].x += s * f.x; acc[1].y += s * f.y;
                f = u32_to_f2((unsigned)pv.z); acc[2].x += s * f.x; acc[2].y += s * f.y;
                f = u32_to_f2((unsigned)pv.w); acc[3].x += s * f.x; acc[3].y += s * f.y;
            }
        } else {
            #pragma unroll 4
            for (int e = start; e < end; ++e) {
                int src = __ldg(&d_csr[e]);
                int4 pv = __ldg(in + src * 8 + gl);
                float2 f;
                f = u32_to_f2((unsigned)pv.x); acc[0].x += f.x; acc[0].y += f.y;
                f = u32_to_f2((unsigned)pv.y); acc[1].x += f.x; acc[1].y += f.y;
                f = u32_to_f2((unsigned)pv.z); acc[2].x += f.x; acc[2].y += f.y;
                f = u32_to_f2((unsigned)pv.w); acc[3].x += f.x; acc[3].y += f.y;
            }
        }

        float disg = __ldg(&d_dis[grp]);
        float sc = ALPHA * disg;

        int4 rv = __ldg(d_hY + grp * 8 + gl);          // res source
        float o[8];
        {
            const unsigned rw[4] = {(unsigned)rv.x, (unsigned)rv.y, (unsigned)rv.z, (unsigned)rv.w};
            #pragma unroll
            for (int k = 0; k < 4; k++) {
                float2 rf = u32_to_f2(rw[k]);
                o[2*k]   = fminf(fmaxf(sc * acc[k].x + RES_SCALE * rf.x, 0.f), 1.f);
                o[2*k+1] = fminf(fmaxf(sc * acc[k].y + RES_SCALE * rf.y, 0.f), 1.f);
            }
        }
        #pragma unroll
        for (int k = 0; k < 8; k++) nonzero |= (o[k] != 0.f);

        if (last) {
            labelsOut[grp * 16 + gl * 2]     = make_float4(o[0], o[1], o[2], o[3]);
            labelsOut[grp * 16 + gl * 2 + 1] = make_float4(o[4], o[5], o[6], o[7]);
        } else {
            int4* outp = (phase == 0) ? d_hB : d_hC;
            int4 w;    // store dis-premultiplied features for next layer
            w.x = (int)h2_to_u32(__floats2half2_rn(disg * o[0], disg * o[1]));
            w.y = (int)h2_to_u32(__floats2half2_rn(disg * o[2], disg * o[3]));
            w.z = (int)h2_to_u32(__floats2half2_rn(disg * o[4], disg * o[5]));
            w.w = (int)h2_to_u32(__floats2half2_rn(disg * o[6], disg * o[7]));
            outp[grp * 8 + gl] = w;
        }
    }

    if (last) {
        unsigned bmask = __ballot_sync(0xffffffffu, nonzero);
        unsigned gbits = (bmask >> (laneInWarp & ~7)) & 0xFFu;
        if (gl == 0 && grp < n) {
            bool notUpd = (gbits == 0u);
            maskOut[grp] = notUpd ? 1.0f : 0.0f;
            if (notUpd) atomicAdd(&s_cnt, 1);
        }
        __syncthreads();
        if (threadIdx.x == 0 && s_cnt) atomicAdd(cntOut, (float)s_cnt);
    }
}

// ---------------- launch ----------------
extern "C" void kernel_launch(void* const* d_in, const int* in_sizes, int n_in,
                              void* d_out, int out_size) {
    const void*  maskp  = d_in[0];                 // bool [N]
    const float* protos = (const float*)d_in[1];   // [C, D] f32
    const int*   labels = (const int*)d_in[2];     // [N] i32
    const int*   edges  = (const int*)d_in[3];     // [2, E] i32

    int N = in_sizes[0];
    int E = in_sizes[3] / 2;
    const int* row = edges;
    const int* col = edges + E;
    int E4 = E / 4;                                // E = 1.6M, divisible by 4

    float*  out       = (float*)d_out;
    float4* labelsOut = (float4*)out;              // [N*D]
    float*  cntOut    = out + (size_t)N * DD;      // [1]
    float*  maskOut   = cntOut + 1;                // [N]

    void* cntPtr = nullptr;
    cudaGetSymbolAddress(&cntPtr, d_cnt);
    cudaMemsetAsync(cntPtr, 0, (NN + 1) * sizeof(int));   // deg + flag

    k_deg<<<(E4 + 255) / 256, 256>>>((const int4*)col, (const uchar4*)maskp, E4, N / 4);

    int B = (N + 1023) / 1024;
    k_scanA<<<B, 1024>>>(N);
    k_scanB<<<B, 1024>>>(N, B);

    k_scatter<<<(E4 + 255) / 256, 256>>>((const int4*)row, (const int4*)col, E4);
    k_init   <<<((N * 8) + 255) / 256, 256>>>(maskp, (const float4*)protos, labels, cntOut, N);

    int lb = (N * 8 + 255) / 256;
    k_layer<<<lb, 256>>>(0, labelsOut, maskOut, cntOut, N);
    k_layer<<<lb, 256>>>(1, labelsOut, maskOut, cntOut, N);
    k_layer<<<lb, 256>>>(2, labelsOut, maskOut, cntOut, N);
}

// round 9
// speedup vs baseline: 1.8986x; 1.0458x over previous
#include <cuda_runtime.h>
#include <cuda_fp16.h>
#include <cstdint>
#include <climits>

#define NN 100000
#define EE 1600000
#define DD 64
#define ALPHA 0.9f
#define RES_SCALE 0.1f   // (1 - alpha)

// ---------------- helpers ----------------
__device__ __forceinline__ unsigned h2_to_u32(__half2 h) {
    union { __half2 h; unsigned u; } c; c.h = h; return c.u;
}
__device__ __forceinline__ float2 u32_to_f2(unsigned u) {
    union { unsigned u; __half2 h; } c; c.u = u;
    return __half22float2(c.h);
}

// ---------------- static device scratch ----------------
__device__ int4  d_hY[NN * 8];          // initial y (half, unscaled): res + layer-0 input
__device__ int4  d_hB[NN * 8];          // buffer B (stores dis*out)
__device__ int4  d_hC[NN * 8];          // buffer C (stores dis*out)
__device__ int   d_cnt[NN + 1];         // [0,N)=deg, [N]=flagU8 (memset)
__device__ float d_dis[NN];             // deg^{-1/2}
__device__ int   d_off[NN + 1];
__device__ int   d_csr[EE];             // src only (4 B/edge)
__device__ int   d_rank[EE];            // edge rank within its destination
__device__ int   d_agg[128];            // per-block aggregates (sentinel INT_MIN)

// ---------------- kernels ----------------
// degree histogram capturing per-edge rank + mask dtype detect + agg sentinel
__global__ void k_deg(const int4* __restrict__ col4, const uchar4* __restrict__ m,
                      int E4, int n4) {
    int i = blockIdx.x * blockDim.x + threadIdx.x;
    if (i < 128) d_agg[i] = INT_MIN;               // seed lookback sentinels
    if (i < E4) {
        int4 c = col4[i];
        int4 r;
        r.x = atomicAdd(&d_cnt[c.x], 1);
        r.y = atomicAdd(&d_cnt[c.y], 1);
        r.z = atomicAdd(&d_cnt[c.z], 1);
        r.w = atomicAdd(&d_cnt[c.w], 1);
        ((int4*)d_rank)[i] = r;
    }
    if (i < n4) {
        uchar4 v = m[i];
        if (v.y | v.z | v.w) d_cnt[NN] = 1;
    }
}

// single-pass exclusive scan with aggregate lookback; writes off, dis
__global__ void k_scan(int n, int B) {
    __shared__ int sh[1024];
    __shared__ int spref;
    int t = threadIdx.x;
    int b = blockIdx.x;
    int i = b * 1024 + t;

    int v = (i < n) ? d_cnt[i] : 0;
    if (i < n) d_dis[i] = (v > 0) ? rsqrtf((float)v) : 0.0f;
    sh[t] = v;
    __syncthreads();
    // Hillis-Steele inclusive scan
    for (int ofs = 1; ofs < 1024; ofs <<= 1) {
        int x = (t >= ofs) ? sh[t - ofs] : 0;
        __syncthreads();
        sh[t] += x;
        __syncthreads();
    }
    int total = sh[1023];
    if (t == 0) {
        spref = 0;
        atomicExch(&d_agg[b], total);              // publish aggregate
    }
    __syncthreads();
    // lookback: thread t (< b) polls predecessor t's aggregate
    if (t < b) {
        int a;
        do { a = atomicAdd(&d_agg[t], 0); } while (a == INT_MIN);
        atomicAdd(&spref, a);
    }
    __syncthreads();
    int pref = spref;

    if (i < n) d_off[i] = pref + sh[t] - v;
    if (b == B - 1 && t == 1023) d_off[n] = pref + total;
}

__device__ __forceinline__ int4 pack8(float4 a, float4 b) {
    int4 r;
    r.x = (int)h2_to_u32(__floats2half2_rn(a.x, a.y));
    r.y = (int)h2_to_u32(__floats2half2_rn(a.z, a.w));
    r.z = (int)h2_to_u32(__floats2half2_rn(b.x, b.y));
    r.w = (int)h2_to_u32(__floats2half2_rn(b.z, b.w));
    return r;
}

// fused: scatter (first SB blocks) + init y / zero count (remaining blocks)
__global__ void k_build(const int4* __restrict__ row4, const int4* __restrict__ col4, int E4,
                        const void* __restrict__ maskp, const float4* __restrict__ protos,
                        const int* __restrict__ labels, float* __restrict__ cntOut,
                        int n, int SB) {
    if (blockIdx.x < SB) {
        int i = blockIdx.x * blockDim.x + threadIdx.x;
        if (i < E4) {
            int4 c = col4[i];
            int4 r = row4[i];
            int4 k = ((const int4*)d_rank)[i];
            d_csr[__ldg(&d_off[c.x]) + k.x] = r.x;
            d_csr[__ldg(&d_off[c.y]) + k.y] = r.y;
            d_csr[__ldg(&d_off[c.z]) + k.z] = r.z;
            d_csr[__ldg(&d_off[c.w]) + k.w] = r.w;
        }
    } else {
        int idx = (blockIdx.x - SB) * blockDim.x + threadIdx.x;
        if (idx == 0) cntOut[0] = 0.0f;
        if (idx >= n * 8) return;
        int node = idx >> 3;
        int q    = idx & 7;
        bool tr;
        if (d_cnt[NN]) tr = ((const unsigned char*)maskp)[node] != 0;
        else           tr = ((const int*)maskp)[node] != 0;
        float4 p0 = make_float4(0.f, 0.f, 0.f, 0.f), p1 = p0;
        if (tr) {
            int base = labels[node] * 16 + q * 2;
            p0 = protos[base];
            p1 = protos[base + 1];
        }
        d_hY[idx] = pack8(p0, p1);
    }
}

// 8 lanes per node; lane owns 8 features (int4).
// Buffers B/C hold dis-premultiplied features; Y is unscaled.
// phase 0: Y->B (per-edge dis[src]); 1: B->C; 2: C->out (+mask/count).
__global__ __launch_bounds__(256) void k_layer(int phase, float4* __restrict__ labelsOut,
                                               float* __restrict__ maskOut,
                                               float* __restrict__ cntOut, int n) {
    __shared__ int s_cnt;
    if (threadIdx.x == 0) s_cnt = 0;
    __syncthreads();

    int grp  = (blockIdx.x * blockDim.x + threadIdx.x) >> 3;
    int gl   = threadIdx.x & 7;
    int laneInWarp = threadIdx.x & 31;
    bool last = (phase == 2);
    bool nonzero = false;

    if (grp < n) {
        const int4* in = (phase == 0) ? d_hY : ((phase == 1) ? d_hB : d_hC);

        int start = d_off[grp];
        int end   = d_off[grp + 1];
        float2 acc[4] = {{0.f,0.f},{0.f,0.f},{0.f,0.f},{0.f,0.f}};

        if (phase == 0) {
            #pragma unroll 4
            for (int e = start; e < end; ++e) {
                int src = __ldg(&d_csr[e]);            // uniform in group: bcast
                float s = __ldg(&d_dis[src]);
                int4 pv = __ldg(in + src * 8 + gl);
                float2 f;
                f = u32_to_f2((unsigned)pv.x); acc[0].x += s * f.x; acc[0].y += s * f.y;
                f = u32_to_f2((unsigned)pv.y); acc[1].x += s * f.x; acc[1].y += s * f.y;
                f = u32_to_f2((unsigned)pv.z); acc[2].x += s * f.x; acc[2].y += s * f.y;
                f = u32_to_f2((unsigned)pv.w); acc[3].x += s * f.x; acc[3].y += s * f.y;
            }
        } else {
            #pragma unroll 4
            for (int e = start; e < end; ++e) {
                int src = __ldg(&d_csr[e]);
                int4 pv = __ldg(in + src * 8 + gl);
                float2 f;
                f = u32_to_f2((unsigned)pv.x); acc[0].x += f.x; acc[0].y += f.y;
                f = u32_to_f2((unsigned)pv.y); acc[1].x += f.x; acc[1].y += f.y;
                f = u32_to_f2((unsigned)pv.z); acc[2].x += f.x; acc[2].y += f.y;
                f = u32_to_f2((unsigned)pv.w); acc[3].x += f.x; acc[3].y += f.y;
            }
        }

        float disg = __ldg(&d_dis[grp]);
        float sc = ALPHA * disg;

        int4 rv = __ldg(d_hY + grp * 8 + gl);          // res source
        float o[8];
        {
            const unsigned rw[4] = {(unsigned)rv.x, (unsigned)rv.y, (unsigned)rv.z, (unsigned)rv.w};
            #pragma unroll
            for (int k = 0; k < 4; k++) {
                float2 rf = u32_to_f2(rw[k]);
                o[2*k]   = fminf(fmaxf(sc * acc[k].x + RES_SCALE * rf.x, 0.f), 1.f);
                o[2*k+1] = fminf(fmaxf(sc * acc[k].y + RES_SCALE * rf.y, 0.f), 1.f);
            }
        }
        #pragma unroll
        for (int k = 0; k < 8; k++) nonzero |= (o[k] != 0.f);

        if (last) {
            labelsOut[grp * 16 + gl * 2]     = make_float4(o[0], o[1], o[2], o[3]);
            labelsOut[grp * 16 + gl * 2 + 1] = make_float4(o[4], o[5], o[6], o[7]);
        } else {
            int4* outp = (phase == 0) ? d_hB : d_hC;
            int4 w;    // store dis-premultiplied features for next layer
            w.x = (int)h2_to_u32(__floats2half2_rn(disg * o[0], disg * o[1]));
            w.y = (int)h2_to_u32(__floats2half2_rn(disg * o[2], disg * o[3]));
            w.z = (int)h2_to_u32(__floats2half2_rn(disg * o[4], disg * o[5]));
            w.w = (int)h2_to_u32(__floats2half2_rn(disg * o[6], disg * o[7]));
            outp[grp * 8 + gl] = w;
        }
    }

    if (last) {
        unsigned bmask = __ballot_sync(0xffffffffu, nonzero);
        unsigned gbits = (bmask >> (laneInWarp & ~7)) & 0xFFu;
        if (gl == 0 && grp < n) {
            bool notUpd = (gbits == 0u);
            maskOut[grp] = notUpd ? 1.0f : 0.0f;
            if (notUpd) atomicAdd(&s_cnt, 1);
        }
        __syncthreads();
        if (threadIdx.x == 0 && s_cnt) atomicAdd(cntOut, (float)s_cnt);
    }
}

// ---------------- launch ----------------
extern "C" void kernel_launch(void* const* d_in, const int* in_sizes, int n_in,
                              void* d_out, int out_size) {
    const void*  maskp  = d_in[0];                 // bool [N]
    const float* protos = (const float*)d_in[1];   // [C, D] f32
    const int*   labels = (const int*)d_in[2];     // [N] i32
    const int*   edges  = (const int*)d_in[3];     // [2, E] i32

    int N = in_sizes[0];
    int E = in_sizes[3] / 2;
    const int* row = edges;
    const int* col = edges + E;
    int E4 = E / 4;                                // E = 1.6M, divisible by 4

    float*  out       = (float*)d_out;
    float4* labelsOut = (float4*)out;              // [N*D]
    float*  cntOut    = out + (size_t)N * DD;      // [1]
    float*  maskOut   = cntOut + 1;                // [N]

    void* cntPtr = nullptr;
    cudaGetSymbolAddress(&cntPtr, d_cnt);
    cudaMemsetAsync(cntPtr, 0, (NN + 1) * sizeof(int));   // deg + flag

    k_deg<<<(E4 + 255) / 256, 256>>>((const int4*)col, (const uchar4*)maskp, E4, N / 4);

    int B = (N + 1023) / 1024;                     // 98 blocks, all resident
    k_scan<<<B, 1024>>>(N, B);

    int SB = (E4 + 255) / 256;                     // scatter blocks
    int IB = (N * 8 + 255) / 256;                  // init blocks
    k_build<<<SB + IB, 256>>>((const int4*)row, (const int4*)col, E4,
                              maskp, (const float4*)protos, labels, cntOut, N, SB);

    int lb = (N * 8 + 255) / 256;
    k_layer<<<lb, 256>>>(0, labelsOut, maskOut, cntOut, N);
    k_layer<<<lb, 256>>>(1, labelsOut, maskOut, cntOut, N);
    k_layer<<<lb, 256>>>(2, labelsOut, maskOut, cntOut, N);
}